// round 11
// baseline (speedup 1.0000x reference)
#include <cuda_runtime.h>
#include <cuda_fp16.h>
#include <cstdint>
#include <math.h>

// RingAttention out = softmax(Q K^T) V, B=32, SQ=1024, SKV=8192, D=64, fp32.
// R11: M=16/warp, 8 warps (16 warps/SM for latency hiding) + compressed softmax:
//   log2e folded into Q, ex2.approx.f16x2, ones-column MMA row sums,
//   warp-vote rescale skip. Pre-split K/V + cp.async double buffer.

#define B_   32
#define SQ_  1024
#define SKV_ 8192
#define D_   64
#define TQ   128
#define TKV  64
#define NT   (SKV_ / TKV)

#define BLK_BYTES 24576
__device__ uint8_t gKV[(size_t)B_ * NT * BLK_BYTES];   // 96 MB scratch

#define QH_OFF 0
#define QL_OFF 16384
#define STG0   32768
#define KH_OFF 0
#define KL_OFF 8192
#define VH_OFF 16384
#define SMEM_BYTES (32768 + 2 * BLK_BYTES)   // 81920

__device__ __forceinline__ uint32_t smem_u32(const void* p) {
    uint32_t a;
    asm("{ .reg .u64 t; cvta.to.shared.u64 t, %1; cvt.u32.u64 %0, t; }" : "=r"(a) : "l"(p));
    return a;
}
__device__ __forceinline__ void ldsm4(uint32_t r[4], uint32_t a) {
    asm volatile("ldmatrix.sync.aligned.m8n8.x4.shared.b16 {%0,%1,%2,%3}, [%4];"
                 : "=r"(r[0]), "=r"(r[1]), "=r"(r[2]), "=r"(r[3]) : "r"(a));
}
__device__ __forceinline__ void ldsm4t(uint32_t r[4], uint32_t a) {
    asm volatile("ldmatrix.sync.aligned.m8n8.x4.trans.shared.b16 {%0,%1,%2,%3}, [%4];"
                 : "=r"(r[0]), "=r"(r[1]), "=r"(r[2]), "=r"(r[3]) : "r"(a));
}
__device__ __forceinline__ void mma16816h(float* c, const uint32_t* a, uint32_t b0, uint32_t b1) {
    asm volatile("mma.sync.aligned.m16n8k16.row.col.f32.f16.f16.f32 "
                 "{%0,%1,%2,%3}, {%4,%5,%6,%7}, {%8,%9}, {%0,%1,%2,%3};"
                 : "+f"(c[0]), "+f"(c[1]), "+f"(c[2]), "+f"(c[3])
                 : "r"(a[0]), "r"(a[1]), "r"(a[2]), "r"(a[3]), "r"(b0), "r"(b1));
}
__device__ __forceinline__ float ex2f(float x) {
    float r;
    asm("ex2.approx.f32 %0, %1;" : "=f"(r) : "f"(x));
    return r;
}
// pack (x,y) -> f16x2 then elementwise 2^()
__device__ __forceinline__ uint32_t exp2pairh(float x, float y) {
    uint32_t d, r;
    asm("cvt.rn.f16x2.f32 %0, %1, %2;" : "=r"(d) : "f"(y), "f"(x));
    asm("ex2.approx.f16x2 %0, %1;" : "=r"(r) : "r"(d));
    return r;
}
__device__ __forceinline__ uint32_t packh(float x, float y) {
    __half2 h = __floats2half2_rn(x, y);
    return *reinterpret_cast<uint32_t*>(&h);
}
__device__ __forceinline__ void split2h(float x, float y, uint32_t& h, uint32_t& l) {
    __half2 hp = __floats2half2_rn(x, y);
    float rx = x - __half2float(__low2half(hp));
    float ry = y - __half2float(__high2half(hp));
    __half2 lp = __floats2half2_rn(rx, ry);
    h = *reinterpret_cast<uint32_t*>(&hp);
    l = *reinterpret_cast<uint32_t*>(&lp);
}
__device__ __forceinline__ void cvt8h(float4 a, float4 b, uint4& h, uint4& l) {
    split2h(a.x, a.y, h.x, l.x);
    split2h(a.z, a.w, h.y, l.y);
    split2h(b.x, b.y, h.z, l.z);
    split2h(b.z, b.w, h.w, l.w);
}
__device__ __forceinline__ uint4 cvt8h1(float4 a, float4 b) {
    uint4 h;
    h.x = packh(a.x, a.y);
    h.y = packh(a.z, a.w);
    h.z = packh(b.x, b.y);
    h.w = packh(b.z, b.w);
    return h;
}
#define CP_ASYNC16(dst, src) \
    asm volatile("cp.async.cg.shared.global [%0], [%1], 16;" :: "r"(dst), "l"(src))
#define CP_COMMIT() asm volatile("cp.async.commit_group;" ::: "memory")
#define CP_WAIT0()  asm volatile("cp.async.wait_group 0;" ::: "memory")

// ===================== kernel A: split K/V ======================
__global__ __launch_bounds__(256)
void split_kv_kernel(const float* __restrict__ K, const float* __restrict__ V)
{
    const int t = blockIdx.x;
    const int b = blockIdx.y;
    const int tid = threadIdx.x;

    const float* Kt = K + ((size_t)b * SKV_ + (size_t)t * TKV) * D_;
    const float* Vt = V + ((size_t)b * SKV_ + (size_t)t * TKV) * D_;
    uint8_t* blk = gKV + ((size_t)b * NT + t) * BLK_BYTES;

    #pragma unroll
    for (int uu = 0; uu < 2; ++uu) {
        const int u = tid + 256 * uu;
        const int r = u >> 3;
        const int c = u & 7;
        const uint32_t off = (uint32_t)r * 128 + (uint32_t)((c ^ (r & 7)) * 16);
        const float4* kp = (const float4*)(Kt + (size_t)r * D_ + c * 8);
        const float4* vp = (const float4*)(Vt + (size_t)r * D_ + c * 8);
        uint4 h, l;
        cvt8h(kp[0], kp[1], h, l);
        *(uint4*)(blk + KH_OFF + off) = h;
        *(uint4*)(blk + KL_OFF + off) = l;
        *(uint4*)(blk + VH_OFF + off) = cvt8h1(vp[0], vp[1]);
    }
}

// ===================== kernel B: attention ======================
__global__ __launch_bounds__(256, 2)
void attn_mma9_kernel(const float* __restrict__ Q, float* __restrict__ O)
{
    extern __shared__ char sm[];
    const uint32_t smb = smem_u32(sm);
    const int tid  = threadIdx.x;
    const int wid  = tid >> 5;
    const int lane = tid & 31;
    const uint32_t l7  = lane & 7;
    const uint32_t l8  = (lane >> 3) & 1;
    const uint32_t l15 = lane & 15;
    const uint32_t l16 = (uint32_t)lane >> 4;
    const int q0 = blockIdx.x * TQ;
    const int b  = blockIdx.y;

    const uint8_t* blk0 = gKV + (size_t)b * NT * BLK_BYTES;

    // ones-column B fragment (col 0 = 1.0, others 0)
    const uint32_t bones = ((lane >> 2) == 0) ? 0x3C003C00u : 0u;

    // ---- prologue: Q * log2(e) -> smem fp16 hi/lo ----
    {
        const int r = tid >> 1, half = tid & 1;
        const float4* qp = (const float4*)(Q + ((size_t)b * SQ_ + q0 + r) * D_ + half * 32);
        const float LG2E = 1.4426950408889634f;
        #pragma unroll
        for (int c = 0; c < 4; ++c) {
            float4 f0 = qp[2 * c], f1 = qp[2 * c + 1];
            f0.x *= LG2E; f0.y *= LG2E; f0.z *= LG2E; f0.w *= LG2E;
            f1.x *= LG2E; f1.y *= LG2E; f1.z *= LG2E; f1.w *= LG2E;
            uint4 h, l;
            cvt8h(f0, f1, h, l);
            const int cc = 4 * half + c;
            uint32_t x = (uint32_t)((cc ^ (r & 7)) * 16);
            *(uint4*)(sm + QH_OFF + r * 128 + x) = h;
            *(uint4*)(sm + QL_OFF + r * 128 + x) = l;
        }
    }

    // ---- stage 0: cp.async tile 0 (24KB = 6 x 16B per thread) ----
    {
        const uint32_t dst = smb + STG0 + (uint32_t)tid * 16;
        const uint8_t* src = blk0 + (size_t)tid * 16;
        #pragma unroll
        for (int i = 0; i < 6; ++i)
            CP_ASYNC16(dst + i * 4096, src + i * 4096);
        CP_COMMIT();
    }

    const int wrow = wid * 16;
    const uint32_t qrowb = (uint32_t)(wrow + (int)l15) * 128;
    const uint32_t krowb = (8 * l16 + l7) * 128;
    const uint32_t vrowb = l15 * 128;

    float o[8][4];
    float oe[4];                     // ones-column accumulator (row sums)
    #pragma unroll
    for (int i = 0; i < 8; ++i)
        #pragma unroll
        for (int j = 0; j < 4; ++j) o[i][j] = 0.f;
    #pragma unroll
    for (int j = 0; j < 4; ++j) oe[j] = 0.f;
    float m0 = -1e30f, m1 = -1e30f;

    for (int t = 0; t < NT; ++t) {
        CP_WAIT0();
        __syncthreads();

        if (t + 1 < NT) {
            const uint32_t dst = smb + STG0 + (uint32_t)(((t + 1) & 1) * BLK_BYTES)
                                 + (uint32_t)tid * 16;
            const uint8_t* src = blk0 + (size_t)(t + 1) * BLK_BYTES + (size_t)tid * 16;
            #pragma unroll
            for (int i = 0; i < 6; ++i)
                CP_ASYNC16(dst + i * 4096, src + i * 4096);
            CP_COMMIT();
        }

        const uint32_t sbase = smb + STG0 + (uint32_t)((t & 1) * BLK_BYTES);

        // ---- S = Qh Kh^T + Ql Kh^T + Qh Kl^T (fp16, fp32 accum, log2 scale) ----
        float s[8][4];
        #pragma unroll
        for (int i = 0; i < 8; ++i)
            #pragma unroll
            for (int j = 0; j < 4; ++j) s[i][j] = 0.f;

        #pragma unroll
        for (int ks = 0; ks < 4; ++ks) {
            uint32_t qh[4], ql[4];
            const uint32_t qx = ((2 * ks + l16) ^ l7) * 16;
            ldsm4(qh, smb + QH_OFF + qrowb + qx);
            ldsm4(ql, smb + QL_OFF + qrowb + qx);
            const uint32_t kx = ((2 * ks + l8) ^ l7) * 16;
            #pragma unroll
            for (int jp = 0; jp < 4; ++jp) {
                uint32_t kb[4];
                ldsm4(kb, sbase + KH_OFF + krowb + (uint32_t)jp * 2048 + kx);
                mma16816h(s[2 * jp],     qh, kb[0], kb[1]);
                mma16816h(s[2 * jp + 1], qh, kb[2], kb[3]);
                mma16816h(s[2 * jp],     ql, kb[0], kb[1]);
                mma16816h(s[2 * jp + 1], ql, kb[2], kb[3]);
            }
            #pragma unroll
            for (int jp = 0; jp < 4; ++jp) {
                uint32_t kb[4];
                ldsm4(kb, sbase + KL_OFF + krowb + (uint32_t)jp * 2048 + kx);
                mma16816h(s[2 * jp],     qh, kb[0], kb[1]);
                mma16816h(s[2 * jp + 1], qh, kb[2], kb[3]);
            }
        }

        // ---- online max (log2 domain) ----
        float m0t = s[0][0], m1t = s[0][2];
        #pragma unroll
        for (int j = 0; j < 8; ++j) {
            m0t = fmaxf(m0t, fmaxf(s[j][0], s[j][1]));
            m1t = fmaxf(m1t, fmaxf(s[j][2], s[j][3]));
        }
        m0t = fmaxf(m0t, __shfl_xor_sync(0xffffffffu, m0t, 1));
        m0t = fmaxf(m0t, __shfl_xor_sync(0xffffffffu, m0t, 2));
        m1t = fmaxf(m1t, __shfl_xor_sync(0xffffffffu, m1t, 1));
        m1t = fmaxf(m1t, __shfl_xor_sync(0xffffffffu, m1t, 2));

        const float m0n = fmaxf(m0, m0t);
        const float m1n = fmaxf(m1, m1t);
        const float a0 = ex2f(m0 - m0n);
        const float a1 = ex2f(m1 - m1n);
        m0 = m0n; m1 = m1n;

        if (__any_sync(0xffffffffu, (a0 < 1.f) || (a1 < 1.f))) {
            #pragma unroll
            for (int nb = 0; nb < 8; ++nb) {
                o[nb][0] *= a0; o[nb][1] *= a0;
                o[nb][2] *= a1; o[nb][3] *= a1;
            }
            oe[0] *= a0; oe[1] *= a0;
            oe[2] *= a1; oe[3] *= a1;
        }

        // ---- P = 2^(s - m) in fp16 (cvt-pack + f16x2 MUFU) ----
        uint32_t ph[8][2];
        #pragma unroll
        for (int j = 0; j < 8; ++j) {
            ph[j][0] = exp2pairh(s[j][0] - m0n, s[j][1] - m0n);
            ph[j][1] = exp2pairh(s[j][2] - m1n, s[j][3] - m1n);
        }

        // ---- O += P V (+ ones column for row sums) ----
        #pragma unroll
        for (int kb = 0; kb < 4; ++kb) {
            uint32_t ah[4] = { ph[2 * kb][0], ph[2 * kb][1],
                               ph[2 * kb + 1][0], ph[2 * kb + 1][1] };
            const uint32_t vb_row = vrowb + (uint32_t)kb * 2048;
            #pragma unroll
            for (int np = 0; np < 4; ++np) {
                uint32_t vb[4];
                ldsm4t(vb, sbase + VH_OFF + vb_row + (((2 * np + l16) ^ l7) * 16));
                mma16816h(o[2 * np],     ah, vb[0], vb[1]);
                mma16816h(o[2 * np + 1], ah, vb[2], vb[3]);
            }
            mma16816h(oe, ah, bones, bones);
        }
    }

    // ---- epilogue: row sums live in oe at lanes lane%4==0; broadcast ----
    const int srcl = lane & ~3;
    const float ls0 = __shfl_sync(0xffffffffu, oe[0], srcl);
    const float ls1 = __shfl_sync(0xffffffffu, oe[2], srcl);
    const float inv0 = 1.f / ls0;
    const float inv1 = 1.f / ls1;

    const int grow = q0 + wrow + (lane >> 2);
    float* op0 = O + ((size_t)b * SQ_ + grow) * D_ + 2 * (lane & 3);
    float* op1 = op0 + 8 * D_;
    #pragma unroll
    for (int nb = 0; nb < 8; ++nb) {
        *(float2*)(op0 + 8 * nb) = make_float2(o[nb][0] * inv0, o[nb][1] * inv0);
        *(float2*)(op1 + 8 * nb) = make_float2(o[nb][2] * inv1, o[nb][3] * inv1);
    }
}

extern "C" void kernel_launch(void* const* d_in, const int* in_sizes, int n_in,
                              void* d_out, int out_size)
{
    (void)in_sizes; (void)n_in; (void)out_size;
    const float* q = (const float*)d_in[0];
    const float* k = (const float*)d_in[1];
    const float* v = (const float*)d_in[2];
    float* o = (float*)d_out;

    dim3 sgrid(NT, B_);
    split_kv_kernel<<<sgrid, 256>>>(k, v);

    cudaFuncSetAttribute(attn_mma9_kernel,
                         cudaFuncAttributeMaxDynamicSharedMemorySize, SMEM_BYTES);
    dim3 grid(SQ_ / TQ, B_);
    attn_mma9_kernel<<<grid, 256, SMEM_BYTES>>>(q, o);
}

// round 12
// speedup vs baseline: 1.0324x; 1.0324x over previous
#include <cuda_runtime.h>
#include <cuda_fp16.h>
#include <cstdint>
#include <math.h>

// RingAttention out = softmax(Q K^T) V, B=32, SQ=1024, SKV=8192, D=64, fp32.
// R12: M=32/warp (4 warps). Latency-covering schedule:
//   phase1: S(mb0) full + S(mb1) ks0-1
//   phase2: mb0 max-tree/shfl (issued first) + S(mb1) ks2-3 + mb0 exp
//   phase3: mb1 max-tree/shfl + O(mb0) + mb1 exp
//   phase4: O(mb1)
// ones-column MMA dropped; row sums via HADD2 on P fragments (fma pipe).

#define B_   32
#define SQ_  1024
#define SKV_ 8192
#define D_   64
#define TQ   128
#define TKV  64
#define NT   (SKV_ / TKV)

#define BLK_BYTES 24576
__device__ uint8_t gKV[(size_t)B_ * NT * BLK_BYTES];   // 96 MB scratch

#define QH_OFF 0
#define QL_OFF 16384
#define STG0   32768
#define KH_OFF 0
#define KL_OFF 8192
#define VH_OFF 16384
#define SMEM_BYTES (32768 + 2 * BLK_BYTES)   // 81920

__device__ __forceinline__ uint32_t smem_u32(const void* p) {
    uint32_t a;
    asm("{ .reg .u64 t; cvta.to.shared.u64 t, %1; cvt.u32.u64 %0, t; }" : "=r"(a) : "l"(p));
    return a;
}
__device__ __forceinline__ void ldsm4(uint32_t r[4], uint32_t a) {
    asm volatile("ldmatrix.sync.aligned.m8n8.x4.shared.b16 {%0,%1,%2,%3}, [%4];"
                 : "=r"(r[0]), "=r"(r[1]), "=r"(r[2]), "=r"(r[3]) : "r"(a));
}
__device__ __forceinline__ void ldsm4t(uint32_t r[4], uint32_t a) {
    asm volatile("ldmatrix.sync.aligned.m8n8.x4.trans.shared.b16 {%0,%1,%2,%3}, [%4];"
                 : "=r"(r[0]), "=r"(r[1]), "=r"(r[2]), "=r"(r[3]) : "r"(a));
}
__device__ __forceinline__ void mma16816h(float* c, const uint32_t* a, uint32_t b0, uint32_t b1) {
    asm volatile("mma.sync.aligned.m16n8k16.row.col.f32.f16.f16.f32 "
                 "{%0,%1,%2,%3}, {%4,%5,%6,%7}, {%8,%9}, {%0,%1,%2,%3};"
                 : "+f"(c[0]), "+f"(c[1]), "+f"(c[2]), "+f"(c[3])
                 : "r"(a[0]), "r"(a[1]), "r"(a[2]), "r"(a[3]), "r"(b0), "r"(b1));
}
__device__ __forceinline__ float ex2f(float x) {
    float r;
    asm("ex2.approx.f32 %0, %1;" : "=f"(r) : "f"(x));
    return r;
}
__device__ __forceinline__ uint32_t exp2pairh(float x, float y) {
    uint32_t d, r;
    asm("cvt.rn.f16x2.f32 %0, %1, %2;" : "=r"(d) : "f"(y), "f"(x));
    asm("ex2.approx.f16x2 %0, %1;" : "=r"(r) : "r"(d));
    return r;
}
__device__ __forceinline__ uint32_t packh(float x, float y) {
    __half2 h = __floats2half2_rn(x, y);
    return *reinterpret_cast<uint32_t*>(&h);
}
__device__ __forceinline__ void split2h(float x, float y, uint32_t& h, uint32_t& l) {
    __half2 hp = __floats2half2_rn(x, y);
    float rx = x - __half2float(__low2half(hp));
    float ry = y - __half2float(__high2half(hp));
    __half2 lp = __floats2half2_rn(rx, ry);
    h = *reinterpret_cast<uint32_t*>(&hp);
    l = *reinterpret_cast<uint32_t*>(&lp);
}
__device__ __forceinline__ void cvt8h(float4 a, float4 b, uint4& h, uint4& l) {
    split2h(a.x, a.y, h.x, l.x);
    split2h(a.z, a.w, h.y, l.y);
    split2h(b.x, b.y, h.z, l.z);
    split2h(b.z, b.w, h.w, l.w);
}
__device__ __forceinline__ uint4 cvt8h1(float4 a, float4 b) {
    uint4 h;
    h.x = packh(a.x, a.y);
    h.y = packh(a.z, a.w);
    h.z = packh(b.x, b.y);
    h.w = packh(b.z, b.w);
    return h;
}
// sum the two fp16 halves of 8 packed values -> (sum_low_halves, sum_high_halves)
__device__ __forceinline__ float2 hsum8(const uint32_t* p, int stride) {
    __half2 a0 = __hadd2(*(const __half2*)&p[0 * stride], *(const __half2*)&p[1 * stride]);
    __half2 a1 = __hadd2(*(const __half2*)&p[2 * stride], *(const __half2*)&p[3 * stride]);
    __half2 a2 = __hadd2(*(const __half2*)&p[4 * stride], *(const __half2*)&p[5 * stride]);
    __half2 a3 = __hadd2(*(const __half2*)&p[6 * stride], *(const __half2*)&p[7 * stride]);
    __half2 s = __hadd2(__hadd2(a0, a1), __hadd2(a2, a3));
    return __half22float2(s);
}
#define CP_ASYNC16(dst, src) \
    asm volatile("cp.async.cg.shared.global [%0], [%1], 16;" :: "r"(dst), "l"(src))
#define CP_COMMIT() asm volatile("cp.async.commit_group;" ::: "memory")
#define CP_WAIT0()  asm volatile("cp.async.wait_group 0;" ::: "memory")

// ===================== kernel A: split K/V ======================
__global__ __launch_bounds__(256)
void split_kv_kernel(const float* __restrict__ K, const float* __restrict__ V)
{
    const int t = blockIdx.x;
    const int b = blockIdx.y;
    const int tid = threadIdx.x;

    const float* Kt = K + ((size_t)b * SKV_ + (size_t)t * TKV) * D_;
    const float* Vt = V + ((size_t)b * SKV_ + (size_t)t * TKV) * D_;
    uint8_t* blk = gKV + ((size_t)b * NT + t) * BLK_BYTES;

    #pragma unroll
    for (int uu = 0; uu < 2; ++uu) {
        const int u = tid + 256 * uu;
        const int r = u >> 3;
        const int c = u & 7;
        const uint32_t off = (uint32_t)r * 128 + (uint32_t)((c ^ (r & 7)) * 16);
        const float4* kp = (const float4*)(Kt + (size_t)r * D_ + c * 8);
        const float4* vp = (const float4*)(Vt + (size_t)r * D_ + c * 8);
        uint4 h, l;
        cvt8h(kp[0], kp[1], h, l);
        *(uint4*)(blk + KH_OFF + off) = h;
        *(uint4*)(blk + KL_OFF + off) = l;
        *(uint4*)(blk + VH_OFF + off) = cvt8h1(vp[0], vp[1]);
    }
}

// ===================== kernel B: attention ======================
__global__ __launch_bounds__(128, 2)
void attn_mma10_kernel(const float* __restrict__ Q, float* __restrict__ O)
{
    extern __shared__ char sm[];
    const uint32_t smb = smem_u32(sm);
    const int tid  = threadIdx.x;
    const int wid  = tid >> 5;
    const int lane = tid & 31;
    const uint32_t l7  = lane & 7;
    const uint32_t l8  = (lane >> 3) & 1;
    const uint32_t l15 = lane & 15;
    const uint32_t l16 = (uint32_t)lane >> 4;
    const int q0 = blockIdx.x * TQ;
    const int b  = blockIdx.y;

    const uint8_t* blk0 = gKV + (size_t)b * NT * BLK_BYTES;

    // ---- prologue: Q * log2(e) -> smem fp16 hi/lo ----
    {
        const float4* qp = (const float4*)(Q + ((size_t)b * SQ_ + q0 + tid) * D_);
        const float LG2E = 1.4426950408889634f;
        #pragma unroll
        for (int c = 0; c < 8; ++c) {
            float4 f0 = qp[2 * c], f1 = qp[2 * c + 1];
            f0.x *= LG2E; f0.y *= LG2E; f0.z *= LG2E; f0.w *= LG2E;
            f1.x *= LG2E; f1.y *= LG2E; f1.z *= LG2E; f1.w *= LG2E;
            uint4 h, l;
            cvt8h(f0, f1, h, l);
            uint32_t x = (uint32_t)((c ^ (tid & 7)) * 16);
            *(uint4*)(sm + QH_OFF + tid * 128 + x) = h;
            *(uint4*)(sm + QL_OFF + tid * 128 + x) = l;
        }
    }
    __syncthreads();

    uint32_t qhr[2][4][4];
    #pragma unroll
    for (int mb = 0; mb < 2; ++mb)
        #pragma unroll
        for (int ks = 0; ks < 4; ++ks) {
            uint32_t a = smb + QH_OFF
                       + (uint32_t)(wid * 32 + mb * 16 + (int)l15) * 128
                       + (((2u * ks + l16) ^ l7) * 16);
            ldsm4(qhr[mb][ks], a);
        }

    {
        const uint32_t dst = smb + STG0 + (uint32_t)tid * 16;
        const uint8_t* src = blk0 + (size_t)tid * 16;
        #pragma unroll
        for (int i = 0; i < 12; ++i)
            CP_ASYNC16(dst + i * 2048, src + i * 2048);
        CP_COMMIT();
    }

    const uint32_t krowb = (8 * l16 + l7) * 128;
    const uint32_t vrowb = l15 * 128;
    const uint32_t qlrow = (uint32_t)(wid * 32 + (int)l15) * 128;

    float o[2][8][4];
    float ls[2][2];          // row-sum partials (this thread's 16 cols)
    #pragma unroll
    for (int mb = 0; mb < 2; ++mb) {
        #pragma unroll
        for (int nb = 0; nb < 8; ++nb)
            #pragma unroll
            for (int c = 0; c < 4; ++c) o[mb][nb][c] = 0.f;
        ls[mb][0] = 0.f; ls[mb][1] = 0.f;
    }
    float m[2][2] = {{-1e30f, -1e30f}, {-1e30f, -1e30f}};

    for (int t = 0; t < NT; ++t) {
        CP_WAIT0();
        __syncthreads();

        if (t + 1 < NT) {
            const uint32_t dst = smb + STG0 + (uint32_t)(((t + 1) & 1) * BLK_BYTES)
                                 + (uint32_t)tid * 16;
            const uint8_t* src = blk0 + (size_t)(t + 1) * BLK_BYTES + (size_t)tid * 16;
            #pragma unroll
            for (int i = 0; i < 12; ++i)
                CP_ASYNC16(dst + i * 2048, src + i * 2048);
            CP_COMMIT();
        }

        const uint32_t sbase = smb + STG0 + (uint32_t)((t & 1) * BLK_BYTES);

        // ======== phase 1: S(mb0) full + S(mb1) ks0-1 ========
        float s0[8][4], s1[8][4];
        #pragma unroll
        for (int nb = 0; nb < 8; ++nb)
            #pragma unroll
            for (int c = 0; c < 4; ++c) { s0[nb][c] = 0.f; s1[nb][c] = 0.f; }

        #pragma unroll
        for (int ks = 0; ks < 4; ++ks) {
            const uint32_t qx = ((2u * ks + l16) ^ l7) * 16;
            const uint32_t kx = ((2u * ks + l8) ^ l7) * 16;
            uint32_t ql0[4], ql1[4];
            ldsm4(ql0, smb + QL_OFF + qlrow + qx);
            if (ks < 2) ldsm4(ql1, smb + QL_OFF + qlrow + 2048 + qx);
            #pragma unroll
            for (int jp = 0; jp < 4; ++jp) {
                uint32_t kh4[4], kl4[4];
                ldsm4(kh4, sbase + KH_OFF + krowb + (uint32_t)jp * 2048 + kx);
                ldsm4(kl4, sbase + KL_OFF + krowb + (uint32_t)jp * 2048 + kx);
                mma16816h(s0[2 * jp],     qhr[0][ks], kh4[0], kh4[1]);
                mma16816h(s0[2 * jp + 1], qhr[0][ks], kh4[2], kh4[3]);
                mma16816h(s0[2 * jp],     ql0, kh4[0], kh4[1]);
                mma16816h(s0[2 * jp + 1], ql0, kh4[2], kh4[3]);
                mma16816h(s0[2 * jp],     qhr[0][ks], kl4[0], kl4[1]);
                mma16816h(s0[2 * jp + 1], qhr[0][ks], kl4[2], kl4[3]);
                if (ks < 2) {
                    mma16816h(s1[2 * jp],     qhr[1][ks], kh4[0], kh4[1]);
                    mma16816h(s1[2 * jp + 1], qhr[1][ks], kh4[2], kh4[3]);
                    mma16816h(s1[2 * jp],     ql1, kh4[0], kh4[1]);
                    mma16816h(s1[2 * jp + 1], ql1, kh4[2], kh4[3]);
                    mma16816h(s1[2 * jp],     qhr[1][ks], kl4[0], kl4[1]);
                    mma16816h(s1[2 * jp + 1], qhr[1][ks], kl4[2], kl4[3]);
                }
            }
        }

        // ======== phase 2: mb0 max/shfl first, S(mb1) ks2-3 fills latency ========
        float m00t = s0[0][0], m01t = s0[0][2];
        #pragma unroll
        for (int nb = 0; nb < 8; ++nb) {
            m00t = fmaxf(m00t, fmaxf(s0[nb][0], s0[nb][1]));
            m01t = fmaxf(m01t, fmaxf(s0[nb][2], s0[nb][3]));
        }
        m00t = fmaxf(m00t, __shfl_xor_sync(0xffffffffu, m00t, 1));
        m00t = fmaxf(m00t, __shfl_xor_sync(0xffffffffu, m00t, 2));
        m01t = fmaxf(m01t, __shfl_xor_sync(0xffffffffu, m01t, 1));
        m01t = fmaxf(m01t, __shfl_xor_sync(0xffffffffu, m01t, 2));

        #pragma unroll
        for (int ks = 2; ks < 4; ++ks) {
            const uint32_t qx = ((2u * ks + l16) ^ l7) * 16;
            const uint32_t kx = ((2u * ks + l8) ^ l7) * 16;
            uint32_t ql1[4];
            ldsm4(ql1, smb + QL_OFF + qlrow + 2048 + qx);
            #pragma unroll
            for (int jp = 0; jp < 4; ++jp) {
                uint32_t kh4[4], kl4[4];
                ldsm4(kh4, sbase + KH_OFF + krowb + (uint32_t)jp * 2048 + kx);
                ldsm4(kl4, sbase + KL_OFF + krowb + (uint32_t)jp * 2048 + kx);
                mma16816h(s1[2 * jp],     qhr[1][ks], kh4[0], kh4[1]);
                mma16816h(s1[2 * jp + 1], qhr[1][ks], kh4[2], kh4[3]);
                mma16816h(s1[2 * jp],     ql1, kh4[0], kh4[1]);
                mma16816h(s1[2 * jp + 1], ql1, kh4[2], kh4[3]);
                mma16816h(s1[2 * jp],     qhr[1][ks], kl4[0], kl4[1]);
                mma16816h(s1[2 * jp + 1], qhr[1][ks], kl4[2], kl4[3]);
            }
        }

        // mb0: rescale + exp
        const float m00n = fmaxf(m[0][0], m00t);
        const float m01n = fmaxf(m[0][1], m01t);
        const float a00 = ex2f(m[0][0] - m00n);
        const float a01 = ex2f(m[0][1] - m01n);
        m[0][0] = m00n; m[0][1] = m01n;
        if (__any_sync(0xffffffffu, (a00 < 1.f) || (a01 < 1.f))) {
            #pragma unroll
            for (int nb = 0; nb < 8; ++nb) {
                o[0][nb][0] *= a00; o[0][nb][1] *= a00;
                o[0][nb][2] *= a01; o[0][nb][3] *= a01;
            }
            ls[0][0] *= a00; ls[0][1] *= a01;
        }
        uint32_t ph0[8][2];
        #pragma unroll
        for (int nb = 0; nb < 8; ++nb) {
            ph0[nb][0] = exp2pairh(s0[nb][0] - m00n, s0[nb][1] - m00n);
            ph0[nb][1] = exp2pairh(s0[nb][2] - m01n, s0[nb][3] - m01n);
        }

        // ======== phase 3: mb1 max/shfl first, O(mb0) fills latency ========
        float m10t = s1[0][0], m11t = s1[0][2];
        #pragma unroll
        for (int nb = 0; nb < 8; ++nb) {
            m10t = fmaxf(m10t, fmaxf(s1[nb][0], s1[nb][1]));
            m11t = fmaxf(m11t, fmaxf(s1[nb][2], s1[nb][3]));
        }
        m10t = fmaxf(m10t, __shfl_xor_sync(0xffffffffu, m10t, 1));
        m10t = fmaxf(m10t, __shfl_xor_sync(0xffffffffu, m10t, 2));
        m11t = fmaxf(m11t, __shfl_xor_sync(0xffffffffu, m11t, 1));
        m11t = fmaxf(m11t, __shfl_xor_sync(0xffffffffu, m11t, 2));

        // row-sum partials for mb0 (HADD2 trees, fma pipe; overlaps O MMAs)
        {
            float2 r0 = hsum8(&ph0[0][0], 2);
            float2 r1 = hsum8(&ph0[0][1], 2);
            ls[0][0] += r0.x + r0.y;
            ls[0][1] += r1.x + r1.y;
        }

        #pragma unroll
        for (int kb = 0; kb < 4; ++kb) {
            uint32_t ah[4] = { ph0[2 * kb][0], ph0[2 * kb][1],
                               ph0[2 * kb + 1][0], ph0[2 * kb + 1][1] };
            const uint32_t vb_row = vrowb + (uint32_t)kb * 2048;
            #pragma unroll
            for (int np = 0; np < 4; ++np) {
                uint32_t vb[4];
                ldsm4t(vb, sbase + VH_OFF + vb_row + (((2u * np + l16) ^ l7) * 16));
                mma16816h(o[0][2 * np],     ah, vb[0], vb[1]);
                mma16816h(o[0][2 * np + 1], ah, vb[2], vb[3]);
            }
        }

        // mb1: rescale + exp
        const float m10n = fmaxf(m[1][0], m10t);
        const float m11n = fmaxf(m[1][1], m11t);
        const float a10 = ex2f(m[1][0] - m10n);
        const float a11 = ex2f(m[1][1] - m11n);
        m[1][0] = m10n; m[1][1] = m11n;
        if (__any_sync(0xffffffffu, (a10 < 1.f) || (a11 < 1.f))) {
            #pragma unroll
            for (int nb = 0; nb < 8; ++nb) {
                o[1][nb][0] *= a10; o[1][nb][1] *= a10;
                o[1][nb][2] *= a11; o[1][nb][3] *= a11;
            }
            ls[1][0] *= a10; ls[1][1] *= a11;
        }
        uint32_t ph1[8][2];
        #pragma unroll
        for (int nb = 0; nb < 8; ++nb) {
            ph1[nb][0] = exp2pairh(s1[nb][0] - m10n, s1[nb][1] - m10n);
            ph1[nb][1] = exp2pairh(s1[nb][2] - m11n, s1[nb][3] - m11n);
        }
        {
            float2 r0 = hsum8(&ph1[0][0], 2);
            float2 r1 = hsum8(&ph1[0][1], 2);
            ls[1][0] += r0.x + r0.y;
            ls[1][1] += r1.x + r1.y;
        }

        // ======== phase 4: O(mb1) ========
        #pragma unroll
        for (int kb = 0; kb < 4; ++kb) {
            uint32_t ah[4] = { ph1[2 * kb][0], ph1[2 * kb][1],
                               ph1[2 * kb + 1][0], ph1[2 * kb + 1][1] };
            const uint32_t vb_row = vrowb + (uint32_t)kb * 2048;
            #pragma unroll
            for (int np = 0; np < 4; ++np) {
                uint32_t vb[4];
                ldsm4t(vb, sbase + VH_OFF + vb_row + (((2u * np + l16) ^ l7) * 16));
                mma16816h(o[1][2 * np],     ah, vb[0], vb[1]);
                mma16816h(o[1][2 * np + 1], ah, vb[2], vb[3]);
            }
        }
    }

    // ---- epilogue: quad-reduce ls partials, normalize, store ----
    #pragma unroll
    for (int mb = 0; mb < 2; ++mb) {
        #pragma unroll
        for (int h = 0; h < 2; ++h) {
            ls[mb][h] += __shfl_xor_sync(0xffffffffu, ls[mb][h], 1);
            ls[mb][h] += __shfl_xor_sync(0xffffffffu, ls[mb][h], 2);
        }
        const float inv0 = 1.f / ls[mb][0];
        const float inv1 = 1.f / ls[mb][1];
        const int row = q0 + wid * 32 + mb * 16 + (lane >> 2);
        float* op0 = O + ((size_t)b * SQ_ + row) * D_ + 2 * (lane & 3);
        float* op1 = op0 + 8 * D_;
        #pragma unroll
        for (int nb = 0; nb < 8; ++nb) {
            *(float2*)(op0 + 8 * nb) = make_float2(o[mb][nb][0] * inv0, o[mb][nb][1] * inv0);
            *(float2*)(op1 + 8 * nb) = make_float2(o[mb][nb][2] * inv1, o[mb][nb][3] * inv1);
        }
    }
}

extern "C" void kernel_launch(void* const* d_in, const int* in_sizes, int n_in,
                              void* d_out, int out_size)
{
    (void)in_sizes; (void)n_in; (void)out_size;
    const float* q = (const float*)d_in[0];
    const float* k = (const float*)d_in[1];
    const float* v = (const float*)d_in[2];
    float* o = (float*)d_out;

    dim3 sgrid(NT, B_);
    split_kv_kernel<<<sgrid, 256>>>(k, v);

    cudaFuncSetAttribute(attn_mma10_kernel,
                         cudaFuncAttributeMaxDynamicSharedMemorySize, SMEM_BYTES);
    dim3 grid(SQ_ / TQ, B_);
    attn_mma10_kernel<<<grid, 128, SMEM_BYTES>>>(q, o);
}

// round 13
// speedup vs baseline: 1.0747x; 1.0409x over previous
#include <cuda_runtime.h>
#include <cuda_fp16.h>
#include <cstdint>
#include <math.h>

// RingAttention out = softmax(Q K^T) V, B=32, SQ=1024, SKV=8192, D=64, fp32.
// R13: R12 body + KV-split x4 (FlashDecoding style) for SM load balance.
//   attn_part: grid (8 qblk, 32 b, 4 chunk), each CTA does 32 KV tiles,
//              writes un-normalized O_partial + per-row (m, l).
//   combine:   merges 4 partials per (b, qblk) item.

#define B_   32
#define SQ_  1024
#define SKV_ 8192
#define D_   64
#define TQ   128
#define TKV  64
#define NT   (SKV_ / TKV)      // 128
#define NCHUNK 4
#define CT   (NT / NCHUNK)     // 32 tiles per chunk
#define NITEM (B_ * SQ_ / TQ)  // 256

#define BLK_BYTES 24576
__device__ uint8_t gKV[(size_t)B_ * NT * BLK_BYTES];            // 96 MB
__device__ float   gOP[(size_t)NITEM * NCHUNK * TQ * D_];       // 32 MB partials
__device__ float2  gML[(size_t)NITEM * NCHUNK * TQ];            // 1 MB (m, l)

#define QH_OFF 0
#define QL_OFF 16384
#define STG0   32768
#define KH_OFF 0
#define KL_OFF 8192
#define VH_OFF 16384
#define SMEM_BYTES (32768 + 2 * BLK_BYTES)   // 81920

__device__ __forceinline__ uint32_t smem_u32(const void* p) {
    uint32_t a;
    asm("{ .reg .u64 t; cvta.to.shared.u64 t, %1; cvt.u32.u64 %0, t; }" : "=r"(a) : "l"(p));
    return a;
}
__device__ __forceinline__ void ldsm4(uint32_t r[4], uint32_t a) {
    asm volatile("ldmatrix.sync.aligned.m8n8.x4.shared.b16 {%0,%1,%2,%3}, [%4];"
                 : "=r"(r[0]), "=r"(r[1]), "=r"(r[2]), "=r"(r[3]) : "r"(a));
}
__device__ __forceinline__ void ldsm4t(uint32_t r[4], uint32_t a) {
    asm volatile("ldmatrix.sync.aligned.m8n8.x4.trans.shared.b16 {%0,%1,%2,%3}, [%4];"
                 : "=r"(r[0]), "=r"(r[1]), "=r"(r[2]), "=r"(r[3]) : "r"(a));
}
__device__ __forceinline__ void mma16816h(float* c, const uint32_t* a, uint32_t b0, uint32_t b1) {
    asm volatile("mma.sync.aligned.m16n8k16.row.col.f32.f16.f16.f32 "
                 "{%0,%1,%2,%3}, {%4,%5,%6,%7}, {%8,%9}, {%0,%1,%2,%3};"
                 : "+f"(c[0]), "+f"(c[1]), "+f"(c[2]), "+f"(c[3])
                 : "r"(a[0]), "r"(a[1]), "r"(a[2]), "r"(a[3]), "r"(b0), "r"(b1));
}
__device__ __forceinline__ float ex2f(float x) {
    float r;
    asm("ex2.approx.f32 %0, %1;" : "=f"(r) : "f"(x));
    return r;
}
__device__ __forceinline__ uint32_t exp2pairh(float x, float y) {
    uint32_t d, r;
    asm("cvt.rn.f16x2.f32 %0, %1, %2;" : "=r"(d) : "f"(y), "f"(x));
    asm("ex2.approx.f16x2 %0, %1;" : "=r"(r) : "r"(d));
    return r;
}
__device__ __forceinline__ uint32_t packh(float x, float y) {
    __half2 h = __floats2half2_rn(x, y);
    return *reinterpret_cast<uint32_t*>(&h);
}
__device__ __forceinline__ void split2h(float x, float y, uint32_t& h, uint32_t& l) {
    __half2 hp = __floats2half2_rn(x, y);
    float rx = x - __half2float(__low2half(hp));
    float ry = y - __half2float(__high2half(hp));
    __half2 lp = __floats2half2_rn(rx, ry);
    h = *reinterpret_cast<uint32_t*>(&hp);
    l = *reinterpret_cast<uint32_t*>(&lp);
}
__device__ __forceinline__ void cvt8h(float4 a, float4 b, uint4& h, uint4& l) {
    split2h(a.x, a.y, h.x, l.x);
    split2h(a.z, a.w, h.y, l.y);
    split2h(b.x, b.y, h.z, l.z);
    split2h(b.z, b.w, h.w, l.w);
}
__device__ __forceinline__ uint4 cvt8h1(float4 a, float4 b) {
    uint4 h;
    h.x = packh(a.x, a.y);
    h.y = packh(a.z, a.w);
    h.z = packh(b.x, b.y);
    h.w = packh(b.z, b.w);
    return h;
}
__device__ __forceinline__ float2 hsum8(const uint32_t* p, int stride) {
    __half2 a0 = __hadd2(*(const __half2*)&p[0 * stride], *(const __half2*)&p[1 * stride]);
    __half2 a1 = __hadd2(*(const __half2*)&p[2 * stride], *(const __half2*)&p[3 * stride]);
    __half2 a2 = __hadd2(*(const __half2*)&p[4 * stride], *(const __half2*)&p[5 * stride]);
    __half2 a3 = __hadd2(*(const __half2*)&p[6 * stride], *(const __half2*)&p[7 * stride]);
    __half2 s = __hadd2(__hadd2(a0, a1), __hadd2(a2, a3));
    return __half22float2(s);
}
#define CP_ASYNC16(dst, src) \
    asm volatile("cp.async.cg.shared.global [%0], [%1], 16;" :: "r"(dst), "l"(src))
#define CP_COMMIT() asm volatile("cp.async.commit_group;" ::: "memory")
#define CP_WAIT0()  asm volatile("cp.async.wait_group 0;" ::: "memory")

// ===================== kernel A: split K/V ======================
__global__ __launch_bounds__(256)
void split_kv_kernel(const float* __restrict__ K, const float* __restrict__ V)
{
    const int t = blockIdx.x;
    const int b = blockIdx.y;
    const int tid = threadIdx.x;

    const float* Kt = K + ((size_t)b * SKV_ + (size_t)t * TKV) * D_;
    const float* Vt = V + ((size_t)b * SKV_ + (size_t)t * TKV) * D_;
    uint8_t* blk = gKV + ((size_t)b * NT + t) * BLK_BYTES;

    #pragma unroll
    for (int uu = 0; uu < 2; ++uu) {
        const int u = tid + 256 * uu;
        const int r = u >> 3;
        const int c = u & 7;
        const uint32_t off = (uint32_t)r * 128 + (uint32_t)((c ^ (r & 7)) * 16);
        const float4* kp = (const float4*)(Kt + (size_t)r * D_ + c * 8);
        const float4* vp = (const float4*)(Vt + (size_t)r * D_ + c * 8);
        uint4 h, l;
        cvt8h(kp[0], kp[1], h, l);
        *(uint4*)(blk + KH_OFF + off) = h;
        *(uint4*)(blk + KL_OFF + off) = l;
        *(uint4*)(blk + VH_OFF + off) = cvt8h1(vp[0], vp[1]);
    }
}

// ===================== kernel B: attention partial ======================
__global__ __launch_bounds__(128, 2)
void attn_part_kernel(const float* __restrict__ Q)
{
    extern __shared__ char sm[];
    const uint32_t smb = smem_u32(sm);
    const int tid  = threadIdx.x;
    const int wid  = tid >> 5;
    const int lane = tid & 31;
    const uint32_t l7  = lane & 7;
    const uint32_t l8  = (lane >> 3) & 1;
    const uint32_t l15 = lane & 15;
    const uint32_t l16 = (uint32_t)lane >> 4;
    const int qblk  = blockIdx.x;
    const int b     = blockIdx.y;
    const int chunk = blockIdx.z;
    const int q0 = qblk * TQ;
    const int t0 = chunk * CT;

    const uint8_t* blk0 = gKV + (size_t)b * NT * BLK_BYTES;

    // ---- prologue: Q * log2(e) -> smem fp16 hi/lo ----
    {
        const float4* qp = (const float4*)(Q + ((size_t)b * SQ_ + q0 + tid) * D_);
        const float LG2E = 1.4426950408889634f;
        #pragma unroll
        for (int c = 0; c < 8; ++c) {
            float4 f0 = qp[2 * c], f1 = qp[2 * c + 1];
            f0.x *= LG2E; f0.y *= LG2E; f0.z *= LG2E; f0.w *= LG2E;
            f1.x *= LG2E; f1.y *= LG2E; f1.z *= LG2E; f1.w *= LG2E;
            uint4 h, l;
            cvt8h(f0, f1, h, l);
            uint32_t x = (uint32_t)((c ^ (tid & 7)) * 16);
            *(uint4*)(sm + QH_OFF + tid * 128 + x) = h;
            *(uint4*)(sm + QL_OFF + tid * 128 + x) = l;
        }
    }
    __syncthreads();

    uint32_t qhr[2][4][4];
    #pragma unroll
    for (int mb = 0; mb < 2; ++mb)
        #pragma unroll
        for (int ks = 0; ks < 4; ++ks) {
            uint32_t a = smb + QH_OFF
                       + (uint32_t)(wid * 32 + mb * 16 + (int)l15) * 128
                       + (((2u * ks + l16) ^ l7) * 16);
            ldsm4(qhr[mb][ks], a);
        }

    {
        const uint32_t dst = smb + STG0 + (uint32_t)tid * 16;
        const uint8_t* src = blk0 + (size_t)t0 * BLK_BYTES + (size_t)tid * 16;
        #pragma unroll
        for (int i = 0; i < 12; ++i)
            CP_ASYNC16(dst + i * 2048, src + i * 2048);
        CP_COMMIT();
    }

    const uint32_t krowb = (8 * l16 + l7) * 128;
    const uint32_t vrowb = l15 * 128;
    const uint32_t qlrow = (uint32_t)(wid * 32 + (int)l15) * 128;

    float o[2][8][4];
    float ls[2][2];
    #pragma unroll
    for (int mb = 0; mb < 2; ++mb) {
        #pragma unroll
        for (int nb = 0; nb < 8; ++nb)
            #pragma unroll
            for (int c = 0; c < 4; ++c) o[mb][nb][c] = 0.f;
        ls[mb][0] = 0.f; ls[mb][1] = 0.f;
    }
    float m[2][2] = {{-1e30f, -1e30f}, {-1e30f, -1e30f}};

    for (int lt = 0; lt < CT; ++lt) {
        const int t = t0 + lt;
        CP_WAIT0();
        __syncthreads();

        if (lt + 1 < CT) {
            const uint32_t dst = smb + STG0 + (uint32_t)(((lt + 1) & 1) * BLK_BYTES)
                                 + (uint32_t)tid * 16;
            const uint8_t* src = blk0 + (size_t)(t + 1) * BLK_BYTES + (size_t)tid * 16;
            #pragma unroll
            for (int i = 0; i < 12; ++i)
                CP_ASYNC16(dst + i * 2048, src + i * 2048);
            CP_COMMIT();
        }

        const uint32_t sbase = smb + STG0 + (uint32_t)((lt & 1) * BLK_BYTES);

        // ======== phase 1: S(mb0) full + S(mb1) ks0-1 ========
        float s0[8][4], s1[8][4];
        #pragma unroll
        for (int nb = 0; nb < 8; ++nb)
            #pragma unroll
            for (int c = 0; c < 4; ++c) { s0[nb][c] = 0.f; s1[nb][c] = 0.f; }

        #pragma unroll
        for (int ks = 0; ks < 4; ++ks) {
            const uint32_t qx = ((2u * ks + l16) ^ l7) * 16;
            const uint32_t kx = ((2u * ks + l8) ^ l7) * 16;
            uint32_t ql0[4], ql1[4];
            ldsm4(ql0, smb + QL_OFF + qlrow + qx);
            if (ks < 2) ldsm4(ql1, smb + QL_OFF + qlrow + 2048 + qx);
            #pragma unroll
            for (int jp = 0; jp < 4; ++jp) {
                uint32_t kh4[4], kl4[4];
                ldsm4(kh4, sbase + KH_OFF + krowb + (uint32_t)jp * 2048 + kx);
                ldsm4(kl4, sbase + KL_OFF + krowb + (uint32_t)jp * 2048 + kx);
                mma16816h(s0[2 * jp],     qhr[0][ks], kh4[0], kh4[1]);
                mma16816h(s0[2 * jp + 1], qhr[0][ks], kh4[2], kh4[3]);
                mma16816h(s0[2 * jp],     ql0, kh4[0], kh4[1]);
                mma16816h(s0[2 * jp + 1], ql0, kh4[2], kh4[3]);
                mma16816h(s0[2 * jp],     qhr[0][ks], kl4[0], kl4[1]);
                mma16816h(s0[2 * jp + 1], qhr[0][ks], kl4[2], kl4[3]);
                if (ks < 2) {
                    mma16816h(s1[2 * jp],     qhr[1][ks], kh4[0], kh4[1]);
                    mma16816h(s1[2 * jp + 1], qhr[1][ks], kh4[2], kh4[3]);
                    mma16816h(s1[2 * jp],     ql1, kh4[0], kh4[1]);
                    mma16816h(s1[2 * jp + 1], ql1, kh4[2], kh4[3]);
                    mma16816h(s1[2 * jp],     qhr[1][ks], kl4[0], kl4[1]);
                    mma16816h(s1[2 * jp + 1], qhr[1][ks], kl4[2], kl4[3]);
                }
            }
        }

        // ======== phase 2: mb0 max/shfl first, S(mb1) ks2-3 fills latency ========
        float m00t = s0[0][0], m01t = s0[0][2];
        #pragma unroll
        for (int nb = 0; nb < 8; ++nb) {
            m00t = fmaxf(m00t, fmaxf(s0[nb][0], s0[nb][1]));
            m01t = fmaxf(m01t, fmaxf(s0[nb][2], s0[nb][3]));
        }
        m00t = fmaxf(m00t, __shfl_xor_sync(0xffffffffu, m00t, 1));
        m00t = fmaxf(m00t, __shfl_xor_sync(0xffffffffu, m00t, 2));
        m01t = fmaxf(m01t, __shfl_xor_sync(0xffffffffu, m01t, 1));
        m01t = fmaxf(m01t, __shfl_xor_sync(0xffffffffu, m01t, 2));

        #pragma unroll
        for (int ks = 2; ks < 4; ++ks) {
            const uint32_t qx = ((2u * ks + l16) ^ l7) * 16;
            const uint32_t kx = ((2u * ks + l8) ^ l7) * 16;
            uint32_t ql1[4];
            ldsm4(ql1, smb + QL_OFF + qlrow + 2048 + qx);
            #pragma unroll
            for (int jp = 0; jp < 4; ++jp) {
                uint32_t kh4[4], kl4[4];
                ldsm4(kh4, sbase + KH_OFF + krowb + (uint32_t)jp * 2048 + kx);
                ldsm4(kl4, sbase + KL_OFF + krowb + (uint32_t)jp * 2048 + kx);
                mma16816h(s1[2 * jp],     qhr[1][ks], kh4[0], kh4[1]);
                mma16816h(s1[2 * jp + 1], qhr[1][ks], kh4[2], kh4[3]);
                mma16816h(s1[2 * jp],     ql1, kh4[0], kh4[1]);
                mma16816h(s1[2 * jp + 1], ql1, kh4[2], kh4[3]);
                mma16816h(s1[2 * jp],     qhr[1][ks], kl4[0], kl4[1]);
                mma16816h(s1[2 * jp + 1], qhr[1][ks], kl4[2], kl4[3]);
            }
        }

        // mb0: rescale + exp
        const float m00n = fmaxf(m[0][0], m00t);
        const float m01n = fmaxf(m[0][1], m01t);
        const float a00 = ex2f(m[0][0] - m00n);
        const float a01 = ex2f(m[0][1] - m01n);
        m[0][0] = m00n; m[0][1] = m01n;
        if (__any_sync(0xffffffffu, (a00 < 1.f) || (a01 < 1.f))) {
            #pragma unroll
            for (int nb = 0; nb < 8; ++nb) {
                o[0][nb][0] *= a00; o[0][nb][1] *= a00;
                o[0][nb][2] *= a01; o[0][nb][3] *= a01;
            }
            ls[0][0] *= a00; ls[0][1] *= a01;
        }
        uint32_t ph0[8][2];
        #pragma unroll
        for (int nb = 0; nb < 8; ++nb) {
            ph0[nb][0] = exp2pairh(s0[nb][0] - m00n, s0[nb][1] - m00n);
            ph0[nb][1] = exp2pairh(s0[nb][2] - m01n, s0[nb][3] - m01n);
        }

        // ======== phase 3: mb1 max/shfl first, O(mb0) fills latency ========
        float m10t = s1[0][0], m11t = s1[0][2];
        #pragma unroll
        for (int nb = 0; nb < 8; ++nb) {
            m10t = fmaxf(m10t, fmaxf(s1[nb][0], s1[nb][1]));
            m11t = fmaxf(m11t, fmaxf(s1[nb][2], s1[nb][3]));
        }
        m10t = fmaxf(m10t, __shfl_xor_sync(0xffffffffu, m10t, 1));
        m10t = fmaxf(m10t, __shfl_xor_sync(0xffffffffu, m10t, 2));
        m11t = fmaxf(m11t, __shfl_xor_sync(0xffffffffu, m11t, 1));
        m11t = fmaxf(m11t, __shfl_xor_sync(0xffffffffu, m11t, 2));

        {
            float2 r0 = hsum8(&ph0[0][0], 2);
            float2 r1 = hsum8(&ph0[0][1], 2);
            ls[0][0] += r0.x + r0.y;
            ls[0][1] += r1.x + r1.y;
        }

        #pragma unroll
        for (int kb = 0; kb < 4; ++kb) {
            uint32_t ah[4] = { ph0[2 * kb][0], ph0[2 * kb][1],
                               ph0[2 * kb + 1][0], ph0[2 * kb + 1][1] };
            const uint32_t vb_row = vrowb + (uint32_t)kb * 2048;
            #pragma unroll
            for (int np = 0; np < 4; ++np) {
                uint32_t vb[4];
                ldsm4t(vb, sbase + VH_OFF + vb_row + (((2u * np + l16) ^ l7) * 16));
                mma16816h(o[0][2 * np],     ah, vb[0], vb[1]);
                mma16816h(o[0][2 * np + 1], ah, vb[2], vb[3]);
            }
        }

        // mb1: rescale + exp
        const float m10n = fmaxf(m[1][0], m10t);
        const float m11n = fmaxf(m[1][1], m11t);
        const float a10 = ex2f(m[1][0] - m10n);
        const float a11 = ex2f(m[1][1] - m11n);
        m[1][0] = m10n; m[1][1] = m11n;
        if (__any_sync(0xffffffffu, (a10 < 1.f) || (a11 < 1.f))) {
            #pragma unroll
            for (int nb = 0; nb < 8; ++nb) {
                o[1][nb][0] *= a10; o[1][nb][1] *= a10;
                o[1][nb][2] *= a11; o[1][nb][3] *= a11;
            }
            ls[1][0] *= a10; ls[1][1] *= a11;
        }
        uint32_t ph1[8][2];
        #pragma unroll
        for (int nb = 0; nb < 8; ++nb) {
            ph1[nb][0] = exp2pairh(s1[nb][0] - m10n, s1[nb][1] - m10n);
            ph1[nb][1] = exp2pairh(s1[nb][2] - m11n, s1[nb][3] - m11n);
        }
        {
            float2 r0 = hsum8(&ph1[0][0], 2);
            float2 r1 = hsum8(&ph1[0][1], 2);
            ls[1][0] += r0.x + r0.y;
            ls[1][1] += r1.x + r1.y;
        }

        // ======== phase 4: O(mb1) ========
        #pragma unroll
        for (int kb = 0; kb < 4; ++kb) {
            uint32_t ah[4] = { ph1[2 * kb][0], ph1[2 * kb][1],
                               ph1[2 * kb + 1][0], ph1[2 * kb + 1][1] };
            const uint32_t vb_row = vrowb + (uint32_t)kb * 2048;
            #pragma unroll
            for (int np = 0; np < 4; ++np) {
                uint32_t vb[4];
                ldsm4t(vb, sbase + VH_OFF + vb_row + (((2u * np + l16) ^ l7) * 16));
                mma16816h(o[1][2 * np],     ah, vb[0], vb[1]);
                mma16816h(o[1][2 * np + 1], ah, vb[2], vb[3]);
            }
        }
    }

    // ---- epilogue: write un-normalized partials + (m, l) ----
    const int cg = ((b * (SQ_ / TQ) + qblk) * NCHUNK + chunk);
    float* obase = gOP + (size_t)cg * TQ * D_;

    #pragma unroll
    for (int mb = 0; mb < 2; ++mb) {
        #pragma unroll
        for (int h = 0; h < 2; ++h) {
            ls[mb][h] += __shfl_xor_sync(0xffffffffu, ls[mb][h], 1);
            ls[mb][h] += __shfl_xor_sync(0xffffffffu, ls[mb][h], 2);
        }
        const int row = wid * 32 + mb * 16 + (lane >> 2);
        float* op0 = obase + (size_t)row * D_ + 2 * (lane & 3);
        float* op1 = op0 + 8 * D_;
        #pragma unroll
        for (int nb = 0; nb < 8; ++nb) {
            *(float2*)(op0 + 8 * nb) = make_float2(o[mb][nb][0], o[mb][nb][1]);
            *(float2*)(op1 + 8 * nb) = make_float2(o[mb][nb][2], o[mb][nb][3]);
        }
        if ((lane & 3) == 0) {
            gML[(size_t)cg * TQ + row]     = make_float2(m[mb][0], ls[mb][0]);
            gML[(size_t)cg * TQ + row + 8] = make_float2(m[mb][1], ls[mb][1]);
        }
    }
}

// ===================== kernel C: combine partials ======================
__global__ __launch_bounds__(128)
void combine_kernel(float* __restrict__ O)
{
    const int item = blockIdx.x;          // 0..255
    const int row  = threadIdx.x;         // 0..127
    const int b    = item >> 3;
    const int qblk = item & 7;

    float mv[NCHUNK], lv[NCHUNK];
    float M = -1e30f;
    #pragma unroll
    for (int q = 0; q < NCHUNK; ++q) {
        float2 p = gML[(size_t)(item * NCHUNK + q) * TQ + row];
        mv[q] = p.x; lv[q] = p.y;
        M = fmaxf(M, mv[q]);
    }
    float w[NCHUNK], L = 0.f;
    #pragma unroll
    for (int q = 0; q < NCHUNK; ++q) {
        w[q] = ex2f(mv[q] - M);
        L += w[q] * lv[q];
    }
    const float inv = 1.f / L;
    #pragma unroll
    for (int q = 0; q < NCHUNK; ++q) w[q] *= inv;

    const float4* src0 = (const float4*)(gOP + (size_t)(item * NCHUNK + 0) * TQ * D_ + (size_t)row * D_);
    const float4* src1 = (const float4*)(gOP + (size_t)(item * NCHUNK + 1) * TQ * D_ + (size_t)row * D_);
    const float4* src2 = (const float4*)(gOP + (size_t)(item * NCHUNK + 2) * TQ * D_ + (size_t)row * D_);
    const float4* src3 = (const float4*)(gOP + (size_t)(item * NCHUNK + 3) * TQ * D_ + (size_t)row * D_);
    float4* dst = (float4*)(O + ((size_t)b * SQ_ + qblk * TQ + row) * D_);

    #pragma unroll
    for (int c = 0; c < D_ / 4; ++c) {
        float4 a0 = src0[c], a1 = src1[c], a2 = src2[c], a3 = src3[c];
        float4 r;
        r.x = w[0] * a0.x + w[1] * a1.x + w[2] * a2.x + w[3] * a3.x;
        r.y = w[0] * a0.y + w[1] * a1.y + w[2] * a2.y + w[3] * a3.y;
        r.z = w[0] * a0.z + w[1] * a1.z + w[2] * a2.z + w[3] * a3.z;
        r.w = w[0] * a0.w + w[1] * a1.w + w[2] * a2.w + w[3] * a3.w;
        dst[c] = r;
    }
}

extern "C" void kernel_launch(void* const* d_in, const int* in_sizes, int n_in,
                              void* d_out, int out_size)
{
    (void)in_sizes; (void)n_in; (void)out_size;
    const float* q = (const float*)d_in[0];
    const float* k = (const float*)d_in[1];
    const float* v = (const float*)d_in[2];
    float* o = (float*)d_out;

    dim3 sgrid(NT, B_);
    split_kv_kernel<<<sgrid, 256>>>(k, v);

    cudaFuncSetAttribute(attn_part_kernel,
                         cudaFuncAttributeMaxDynamicSharedMemorySize, SMEM_BYTES);
    dim3 agrid(SQ_ / TQ, B_, NCHUNK);
    attn_part_kernel<<<agrid, 128, SMEM_BYTES>>>(q);

    combine_kernel<<<NITEM, TQ>>>(o);
}